// round 11
// baseline (speedup 1.0000x reference)
#include <cuda_runtime.h>
#include <cuda_fp16.h>
#include <cstdint>
#include <cstddef>

#define DEV __device__ __forceinline__
using f16 = __half;

// ---------------- problem constants ----------------
constexpr int BATCH  = 16384;
constexpr int HDIM   = 1024;
constexpr int INDIM  = 512;
constexpr int OUTDIM = 512;
constexpr int NBLK   = 2;
constexpr float BN_EPS = 1e-3f;

// ---------------- GEMM tiling (R7/R9-proven config) ----------------
constexpr int BM  = 128;
constexpr int BNT = 128;
constexpr int BK  = 64;
constexpr int NTH = 256;          // 8 warps: 4 (m) x 2 (n); warp tile 32x64
constexpr int LDA = BK + 8;       // 72  -> conflict-free ldmatrix
constexpr int LDB = BNT + 8;      // 136
constexpr int A_ELE = BM * LDA;
constexpr int B_ELE = BK * LDB;
constexpr int S_PIPE = 3;
constexpr int GEMM_SMEM = S_PIPE * (A_ELE + B_ELE) * 2;   // 107,520 B -> 2 CTA/SM

// ---------------- persistent device scratch ----------------
__device__ __align__(16) float g_y  [BATCH * HDIM];   // fp32 residual stream
__device__ __align__(16) f16   g_a  [BATCH * HDIM];   // current activation (GEMM1 input)
__device__ __align__(16) f16   g_h  [BATCH * HDIM];   // hidden (GEMM2 input)
__device__ __align__(16) f16   g_yh [BATCH * HDIM];   // fp16 copy of final y (epilogue A)
__device__ __align__(16) f16   g_x  [BATCH * INDIM];
__device__ __align__(16) f16   g_w1 [NBLK * HDIM * HDIM];  // bn1-folded W1
__device__ __align__(16) f16   g_w2 [NBLK * HDIM * HDIM];
__device__ __align__(16) f16   g_wi [INDIM * HDIM];
__device__ __align__(16) f16   g_wo [HDIM * OUTDIM];
__device__ __align__(16) float g_inv[NBLK * 2 * HDIM];
__device__ __align__(16) float g_b1f[NBLK * HDIM];        // bn1-folded b1

// ---------------- small helpers ----------------
DEV uint32_t sptr(const void* p) { return (uint32_t)__cvta_generic_to_shared(p); }

DEV void ldm4(uint32_t r[4], uint32_t a) {
    asm volatile("ldmatrix.sync.aligned.m8n8.x4.shared.b16 {%0,%1,%2,%3}, [%4];"
                 : "=r"(r[0]), "=r"(r[1]), "=r"(r[2]), "=r"(r[3]) : "r"(a));
}
DEV void ldm4t(uint32_t r[4], uint32_t a) {
    asm volatile("ldmatrix.sync.aligned.m8n8.x4.trans.shared.b16 {%0,%1,%2,%3}, [%4];"
                 : "=r"(r[0]), "=r"(r[1]), "=r"(r[2]), "=r"(r[3]) : "r"(a));
}
DEV void mma16816(float d[4], const uint32_t a[4], const uint32_t b[2]) {
    asm volatile("mma.sync.aligned.m16n8k16.row.col.f32.f16.f16.f32 "
                 "{%0,%1,%2,%3}, {%4,%5,%6,%7}, {%8,%9}, {%0,%1,%2,%3};"
                 : "+f"(d[0]), "+f"(d[1]), "+f"(d[2]), "+f"(d[3])
                 : "r"(a[0]), "r"(a[1]), "r"(a[2]), "r"(a[3]), "r"(b[0]), "r"(b[1]));
}
DEV uint32_t packh(float a, float b) {
    __half2 t = __floats2half2_rn(a, b);
    return *reinterpret_cast<uint32_t*>(&t);
}

DEV void cpa(uint32_t dst, const void* src) {
    asm volatile("cp.async.cg.shared.global [%0], [%1], 16;\n" :: "r"(dst), "l"(src));
}
DEV void cpc() { asm volatile("cp.async.commit_group;\n"); }
template <int N> DEV void cpw() { asm volatile("cp.async.wait_group %0;\n" :: "n"(N)); }

// PDL primitives
DEV void gdc_wait()   { asm volatile("griddepcontrol.wait;" ::: "memory"); }
DEV void gdc_launch() { asm volatile("griddepcontrol.launch_dependents;" ::: "memory"); }

// ---------------- unified pipelined fp16 GEMM ----------------
// A: [M,K] f16, B: [K,N] f16, fp32 accumulate. v = acc + bias.
// MODE 0: Cf = v fp32; if Ab: Ab = relu(bn(v))            [prologue / epilogue]
// MODE 1: Cb = relu(v) f16 (bn1 pre-folded into W1/b1)    [ODE GEMM #1 -> h]
// MODE 3: t = relu(yin + v);                              [Euler block finish]
//         if Cf: Cf = t fp32; if Ab: Ab = relu(bn(t)); if Ch: Ch = t f16
// BIND: B operand is independent of the immediate predecessor -> prefetch
//       its first stages before griddepcontrol.wait.
//
// Convoy breaking: each warp walks the 4 K-slices of a tile in a rotated
// order (phase = warp & 3). Accumulation over K is order-independent, and
// the rotation de-phases LDSM bursts vs MMA bursts across warps so the L1
// and tensor pipes overlap instead of alternating.
template <int MODE, bool BIND>
__global__ void __launch_bounds__(NTH, 2)
gemm_f16(const f16* __restrict__ A, const f16* __restrict__ B,
         const float* __restrict__ bias,
         const float* __restrict__ mn, const float* __restrict__ iv, const float* __restrict__ bt,
         const float* __restrict__ yin,
         float* __restrict__ Cf, f16* __restrict__ Cb, f16* __restrict__ Ab,
         f16* __restrict__ Ch,
         int M, int K, int N)
{
    constexpr int SSET = A_ELE + B_ELE;
    constexpr int NSL = BK / 16;   // 4 K-slices per tile
    extern __shared__ __align__(16) f16 smem[];

    const int tid = threadIdx.x, lane = tid & 31, warp = tid >> 5;
    const int wm = warp >> 1, wn = warp & 1;
    const int phase = warp & (NSL - 1);
    const int m0 = blockIdx.y * BM, n0 = blockIdx.x * BNT;

    auto stA = [&](int s) -> f16* { return smem + s * SSET; };
    auto stB = [&](int s) -> f16* { return smem + s * SSET + A_ELE; };

    auto load_A = [&](int s, int kt) {
        const size_t kof = (size_t)kt * BK;
#pragma unroll
        for (int i = 0; i < 4; i++) {              // A: 128 rows x 8 chunks of 16B
            const int ch = tid + i * NTH;
            const int r = ch >> 3, c = (ch & 7) * 8;
            cpa(sptr(stA(s) + r * LDA + c), A + (size_t)(m0 + r) * K + kof + c);
        }
    };
    auto load_B = [&](int s, int kt) {
        const size_t kof = (size_t)kt * BK;
#pragma unroll
        for (int i = 0; i < 4; i++) {              // B: 64 rows x 16 chunks of 16B
            const int ch = tid + i * NTH;
            const int r = ch >> 4, c = (ch & 15) * 8;
            cpa(sptr(stB(s) + r * LDB + c), B + (kof + r) * (size_t)N + n0 + c);
        }
    };
    auto load_tile = [&](int s, int kt) { load_A(s, kt); load_B(s, kt); };

    float acc[2][8][4] = {};
    const int KT = K / BK;

    // ---- pipeline prologue with PDL overlap ----
    if constexpr (BIND) {
        // B (weights) independent of immediate predecessor: prefetch during its tail
        load_B(0, 0);
        load_B(1, 1);
        gdc_wait();
        load_A(0, 0); cpc();    // group0 = {B0, B1, A0}
        load_A(1, 1); cpc();    // group1 = {A1}
    } else {
        gdc_wait();
        for (int s = 0; s < S_PIPE - 1; s++) { load_tile(s, s); cpc(); }
    }

    for (int kt = 0; kt < KT; kt++) {
        cpw<S_PIPE - 2>();
        __syncthreads();   // data ready + all warps done with the stage being overwritten
        const int nkt = kt + S_PIPE - 1;
        if (nkt < KT) load_tile(nkt % S_PIPE, nkt);
        cpc();

        const int rs = kt % S_PIPE;
        const f16* aS = stA(rs);
        const f16* bS = stB(rs);

        // register double-buffered fragment pipeline over rotated slices
        uint32_t aF[2][2][4], bF[2][8][2];
        auto ldf = [&](int bb, int sl) {
            const int ks = ((sl + phase) & (NSL - 1)) * 16;
#pragma unroll
            for (int mt = 0; mt < 2; mt++) {
                const int r = wm * 32 + mt * 16 + (lane & 15);
                const int c = ks + ((lane >> 4) << 3);
                ldm4(aF[bb][mt], sptr(aS + r * LDA + c));
            }
#pragma unroll
            for (int np = 0; np < 4; np++) {
                const int r = ks + (((lane >> 3) & 1) << 3) + (lane & 7);
                const int c = wn * 64 + np * 16 + ((lane >> 4) << 3);
                uint32_t t[4];
                ldm4t(t, sptr(bS + r * LDB + c));
                bF[bb][np * 2][0] = t[0]; bF[bb][np * 2][1] = t[1];
                bF[bb][np * 2 + 1][0] = t[2]; bF[bb][np * 2 + 1][1] = t[3];
            }
        };
        ldf(0, 0);
#pragma unroll
        for (int ksi = 0; ksi < NSL; ksi++) {
            if (ksi + 1 < NSL) ldf((ksi + 1) & 1, ksi + 1);
            const int cur = ksi & 1;
#pragma unroll
            for (int mt = 0; mt < 2; mt++)
#pragma unroll
                for (int nt = 0; nt < 8; nt++)
                    mma16816(acc[mt][nt], aF[cur][mt], bF[cur][nt]);
        }
        // no tail barrier: next iteration's top barrier provides the ordering
    }

    // ---- epilogue ----
#pragma unroll
    for (int mt = 0; mt < 2; mt++) {
        const int row = m0 + wm * 32 + mt * 16 + (lane >> 2);
#pragma unroll
        for (int nt = 0; nt < 8; nt++) {
            const int col = n0 + wn * 64 + nt * 8 + ((lane & 3) << 1);
            const float2 bs = *reinterpret_cast<const float2*>(bias + col);
            float v0 = acc[mt][nt][0] + bs.x;
            float v1 = acc[mt][nt][1] + bs.y;
            float v2 = acc[mt][nt][2] + bs.x;
            float v3 = acc[mt][nt][3] + bs.y;
            const size_t o0 = (size_t)row * N + col;
            const size_t o1 = (size_t)(row + 8) * N + col;

            if constexpr (MODE == 1) {
                v0 = fmaxf(v0, 0.f);
                v1 = fmaxf(v1, 0.f);
                v2 = fmaxf(v2, 0.f);
                v3 = fmaxf(v3, 0.f);
                *reinterpret_cast<uint32_t*>(Cb + o0) = packh(v0, v1);
                *reinterpret_cast<uint32_t*>(Cb + o1) = packh(v2, v3);
            } else if constexpr (MODE == 3) {
                const float2 y0 = *reinterpret_cast<const float2*>(yin + o0);
                const float2 y1 = *reinterpret_cast<const float2*>(yin + o1);
                float t0 = fmaxf(y0.x + v0, 0.f);
                float t1 = fmaxf(y0.y + v1, 0.f);
                float t2v = fmaxf(y1.x + v2, 0.f);
                float t3 = fmaxf(y1.y + v3, 0.f);
                if (Cf) {
                    *reinterpret_cast<float2*>(Cf + o0) = make_float2(t0, t1);
                    *reinterpret_cast<float2*>(Cf + o1) = make_float2(t2v, t3);
                }
                if (Ab) {
                    const float2 m2 = *reinterpret_cast<const float2*>(mn + col);
                    const float2 i2 = *reinterpret_cast<const float2*>(iv + col);
                    const float2 b2v = *reinterpret_cast<const float2*>(bt + col);
                    float a0 = fmaxf((t0 - m2.x) * i2.x + b2v.x, 0.f);
                    float a1 = fmaxf((t1 - m2.y) * i2.y + b2v.y, 0.f);
                    float a2 = fmaxf((t2v - m2.x) * i2.x + b2v.x, 0.f);
                    float a3 = fmaxf((t3 - m2.y) * i2.y + b2v.y, 0.f);
                    *reinterpret_cast<uint32_t*>(Ab + o0) = packh(a0, a1);
                    *reinterpret_cast<uint32_t*>(Ab + o1) = packh(a2, a3);
                }
                if (Ch) {
                    *reinterpret_cast<uint32_t*>(Ch + o0) = packh(t0, t1);
                    *reinterpret_cast<uint32_t*>(Ch + o1) = packh(t2v, t3);
                }
            } else {   // MODE 0
                *reinterpret_cast<float2*>(Cf + o0) = make_float2(v0, v1);
                *reinterpret_cast<float2*>(Cf + o1) = make_float2(v2, v3);
                if (Ab) {
                    const float2 m2 = *reinterpret_cast<const float2*>(mn + col);
                    const float2 i2 = *reinterpret_cast<const float2*>(iv + col);
                    const float2 t2 = *reinterpret_cast<const float2*>(bt + col);
                    float a0 = fmaxf((v0 - m2.x) * i2.x + t2.x, 0.f);
                    float a1 = fmaxf((v1 - m2.y) * i2.y + t2.y, 0.f);
                    float a2 = fmaxf((v2 - m2.x) * i2.x + t2.x, 0.f);
                    float a3 = fmaxf((v3 - m2.y) * i2.y + t2.y, 0.f);
                    *reinterpret_cast<uint32_t*>(Ab + o0) = packh(a0, a1);
                    *reinterpret_cast<uint32_t*>(Ab + o1) = packh(a2, a3);
                }
            }
        }
    }

    // allow dependent grid to schedule; our stores above are visible to its gdc_wait
    gdc_launch();
}

// ---------------- prep kernels (2 launches total) ----------------
// inv for all 4 bn layers + bn1-folded b1 for both blocks
__global__ void prep_scalars(const float* __restrict__ gamma, const float* __restrict__ var,
                             const float* __restrict__ b1, const float* __restrict__ mean,
                             const float* __restrict__ beta,
                             float* __restrict__ inv, float* __restrict__ b1f)
{
    int i = blockIdx.x * blockDim.x + threadIdx.x;
    const int NINV = NBLK * 2 * HDIM;
    if (i < NINV) {
        inv[i] = gamma[i] * rsqrtf(var[i] + BN_EPS);
    } else if (i < NINV + NBLK * HDIM) {
        int j = i - NINV;
        int blk = j / HDIM, col = j % HDIM;
        int idx = (blk * 2 + 1) * HDIM + col;
        float ivv = gamma[idx] * rsqrtf(var[idx] + BN_EPS);
        b1f[j] = (b1[j] - mean[idx]) * ivv + beta[idx];
    }
}

// Batched fp32 -> fp16 conversion; W1 segment folds bn1 scale (reads g_inv).
constexpr int SEG_X  = BATCH * INDIM / 4;
constexpr int SEG_WI = INDIM * HDIM / 4;
constexpr int SEG_WO = HDIM * OUTDIM / 4;
constexpr int SEG_W1 = NBLK * HDIM * HDIM / 4;
constexpr int SEG_W2 = NBLK * HDIM * HDIM / 4;
constexpr int SEG_TOTAL = SEG_X + SEG_WI + SEG_WO + SEG_W1 + SEG_W2;

__global__ void conv_all(const float* __restrict__ X,  f16* __restrict__ xo,
                         const float* __restrict__ Wi, f16* __restrict__ wio,
                         const float* __restrict__ Wo, f16* __restrict__ woo,
                         const float* __restrict__ W1, f16* __restrict__ w1o,
                         const float* __restrict__ W2, f16* __restrict__ w2o)
{
    int i = blockIdx.x * blockDim.x + threadIdx.x;
    if (i >= SEG_TOTAL) return;
    int j = i;
    if (j < SEG_X) {
        float4 v = reinterpret_cast<const float4*>(X)[j];
        uint2 o; o.x = packh(v.x, v.y); o.y = packh(v.z, v.w);
        reinterpret_cast<uint2*>(xo)[j] = o;
    } else if ((j -= SEG_X) < SEG_WI) {
        float4 v = reinterpret_cast<const float4*>(Wi)[j];
        uint2 o; o.x = packh(v.x, v.y); o.y = packh(v.z, v.w);
        reinterpret_cast<uint2*>(wio)[j] = o;
    } else if ((j -= SEG_WI) < SEG_WO) {
        float4 v = reinterpret_cast<const float4*>(Wo)[j];
        uint2 o; o.x = packh(v.x, v.y); o.y = packh(v.z, v.w);
        reinterpret_cast<uint2*>(woo)[j] = o;
    } else if ((j -= SEG_WO) < SEG_W1) {
        // fold bn1 column scale into W1
        float4 v = reinterpret_cast<const float4*>(W1)[j];
        const int col = (j * 4) & (HDIM - 1);
        const int blk = (j * 4) / (HDIM * HDIM);
        const float4 s4 = *reinterpret_cast<const float4*>(g_inv + (blk * 2 + 1) * HDIM + col);
        uint2 o;
        o.x = packh(v.x * s4.x, v.y * s4.y);
        o.y = packh(v.z * s4.z, v.w * s4.w);
        reinterpret_cast<uint2*>(w1o)[j] = o;
    } else {
        j -= SEG_W1;
        float4 v = reinterpret_cast<const float4*>(W2)[j];
        uint2 o; o.x = packh(v.x, v.y); o.y = packh(v.z, v.w);
        reinterpret_cast<uint2*>(w2o)[j] = o;
    }
}

// ---------------- host ----------------
template <int MODE, bool BIND>
static void launch_gemm(dim3 grid,
                        const f16* A, const f16* B, const float* bias,
                        const float* mn, const float* iv, const float* bt,
                        const float* yin,
                        float* Cf, f16* Cb, f16* Ab, f16* Ch,
                        int M, int K, int N)
{
    cudaLaunchConfig_t cfg = {};
    cfg.gridDim = grid;
    cfg.blockDim = dim3(NTH);
    cfg.dynamicSmemBytes = GEMM_SMEM;
    cfg.stream = 0;
    cudaLaunchAttribute at;
    at.id = cudaLaunchAttributeProgrammaticStreamSerialization;
    at.val.programmaticStreamSerializationAllowed = 1;
    cfg.attrs = &at;
    cfg.numAttrs = 1;
    cudaLaunchKernelEx(&cfg, gemm_f16<MODE, BIND>,
                       A, B, bias, mn, iv, bt, yin, Cf, Cb, Ab, Ch, M, K, N);
}

extern "C" void kernel_launch(void* const* d_in, const int* in_sizes, int n_in,
                              void* d_out, int out_size)
{
    const float* X        = (const float*)d_in[0];
    const float* W_in     = (const float*)d_in[1];
    const float* b_in     = (const float*)d_in[2];
    const float* bn_gamma = (const float*)d_in[3];
    const float* bn_beta  = (const float*)d_in[4];
    const float* bn_mean  = (const float*)d_in[5];
    const float* bn_var   = (const float*)d_in[6];
    const float* W1       = (const float*)d_in[7];
    const float* b1       = (const float*)d_in[8];
    const float* W2       = (const float*)d_in[9];
    const float* b2       = (const float*)d_in[10];
    const float* W_out    = (const float*)d_in[11];
    const float* b_out    = (const float*)d_in[12];

    float *y, *inv, *b1f;
    f16 *a, *h, *yh, *x, *w1p, *w2p, *wi, *wo;
    cudaGetSymbolAddress((void**)&y,   g_y);
    cudaGetSymbolAddress((void**)&inv, g_inv);
    cudaGetSymbolAddress((void**)&b1f, g_b1f);
    cudaGetSymbolAddress((void**)&a,   g_a);
    cudaGetSymbolAddress((void**)&h,   g_h);
    cudaGetSymbolAddress((void**)&yh,  g_yh);
    cudaGetSymbolAddress((void**)&x,   g_x);
    cudaGetSymbolAddress((void**)&w1p, g_w1);
    cudaGetSymbolAddress((void**)&w2p, g_w2);
    cudaGetSymbolAddress((void**)&wi,  g_wi);
    cudaGetSymbolAddress((void**)&wo,  g_wo);

    cudaFuncSetAttribute(gemm_f16<0, false>, cudaFuncAttributeMaxDynamicSharedMemorySize, GEMM_SMEM);
    cudaFuncSetAttribute(gemm_f16<0, true>,  cudaFuncAttributeMaxDynamicSharedMemorySize, GEMM_SMEM);
    cudaFuncSetAttribute(gemm_f16<1, true>,  cudaFuncAttributeMaxDynamicSharedMemorySize, GEMM_SMEM);
    cudaFuncSetAttribute(gemm_f16<3, true>,  cudaFuncAttributeMaxDynamicSharedMemorySize, GEMM_SMEM);

    // ---- prep (2 launches, plain) ----
    {
        const int n = NBLK * 2 * HDIM + NBLK * HDIM;
        prep_scalars<<<(n + 255) / 256, 256>>>(bn_gamma, bn_var, b1, bn_mean, bn_beta, inv, b1f);
        conv_all<<<(SEG_TOTAL + 255) / 256, 256>>>(X, x, W_in, wi, W_out, wo, W1, w1p, W2, w2p);
    }

    const dim3 gH(HDIM / BNT, BATCH / BM);     // (8, 128)
    const dim3 gO(OUTDIM / BNT, BATCH / BM);   // (4, 128)

    // ---- prologue: y = X@W_in + b_in; a = relu(bn0_b0(y)) ----
    launch_gemm<0, false>(gH, x, wi, b_in,
                          bn_mean, inv, bn_beta, nullptr,
                          y, nullptr, a, nullptr,
                          BATCH, INDIM, HDIM);

    // ---- Forward Euler per block (h = 1), fully fused:
    //   h = relu(a@W1' + b1')                           MODE 1 (bn1 folded)
    //   y = relu(y + (h@W2+b2)); a_next / f16(y)        MODE 3
    for (int b = 0; b < NBLK; ++b) {
        const f16* W1b = w1p + (size_t)b * HDIM * HDIM;
        const f16* W2b = w2p + (size_t)b * HDIM * HDIM;
        const float* b1p = b1f + b * HDIM;
        const float* b2p = b2 + b * HDIM;

        launch_gemm<1, true>(gH, a, W1b, b1p,
                             nullptr, nullptr, nullptr, nullptr,
                             nullptr, h, nullptr, nullptr,
                             BATCH, HDIM, HDIM);

        const bool final_blk = (b == NBLK - 1);
        const int nb2 = ((b + 1) * 2) % (NBLK * 2);
        launch_gemm<3, true>(gH, h, W2b, b2p,
                             bn_mean + (size_t)nb2 * HDIM,
                             inv + nb2 * HDIM,
                             bn_beta + (size_t)nb2 * HDIM,
                             y,
                             final_blk ? nullptr : y,
                             nullptr,
                             final_blk ? nullptr : a,
                             final_blk ? yh : nullptr,
                             BATCH, HDIM, HDIM);
    }

    // ---- epilogue: out = y @ W_out + b_out ----
    launch_gemm<0, true>(gO, yh, wo, b_out,
                         nullptr, nullptr, nullptr, nullptr,
                         (float*)d_out, nullptr, nullptr, nullptr,
                         BATCH, HDIM, OUTDIM);
}

// round 12
// speedup vs baseline: 1.2042x; 1.2042x over previous
#include <cuda_runtime.h>
#include <cuda.h>
#include <cuda_fp16.h>
#include <cstdint>
#include <cstddef>

#define DEV __device__ __forceinline__
using f16 = __half;

// ---------------- problem constants ----------------
constexpr int BATCH  = 16384;
constexpr int HDIM   = 1024;
constexpr int INDIM  = 512;
constexpr int OUTDIM = 512;
constexpr int NBLK   = 2;
constexpr float BN_EPS = 1e-3f;

// ---------------- GEMM tiling (R10-proven shape, TMA staging) ----------------
constexpr int BM  = 128;
constexpr int BNT = 128;
constexpr int BK  = 64;
constexpr int NTH = 256;              // 8 warps: 4 (m) x 2 (n); warp tile 32x64
constexpr int S_PIPE = 3;
constexpr uint32_t STAGE = 32768;     // A 16KB + 2x B-half 8KB, SW128 tiles (128B rows)
constexpr int GEMM_SMEM = S_PIPE * (int)STAGE + 1024;   // 99,328 B -> 2 CTA/SM

// ---------------- persistent device scratch ----------------
__device__ __align__(16) float g_y  [BATCH * HDIM];   // fp32 residual stream
__device__ __align__(16) f16   g_a  [BATCH * HDIM];   // current activation (GEMM1 input)
__device__ __align__(16) f16   g_h  [BATCH * HDIM];   // hidden (GEMM2 input)
__device__ __align__(16) f16   g_yh [BATCH * HDIM];   // fp16 copy of final y (epilogue A)
__device__ __align__(16) f16   g_x  [BATCH * INDIM];
__device__ __align__(16) f16   g_w1 [NBLK * HDIM * HDIM];  // bn1-folded W1
__device__ __align__(16) f16   g_w2 [NBLK * HDIM * HDIM];
__device__ __align__(16) f16   g_wi [INDIM * HDIM];
__device__ __align__(16) f16   g_wo [HDIM * OUTDIM];
__device__ __align__(16) float g_inv[NBLK * 2 * HDIM];
__device__ __align__(16) float g_b1f[NBLK * HDIM];        // bn1-folded b1

// ---------------- device helpers ----------------
DEV uint32_t sptr(const void* p) { return (uint32_t)__cvta_generic_to_shared(p); }

DEV void ldm4(uint32_t r[4], uint32_t a) {
    asm volatile("ldmatrix.sync.aligned.m8n8.x4.shared.b16 {%0,%1,%2,%3}, [%4];"
                 : "=r"(r[0]), "=r"(r[1]), "=r"(r[2]), "=r"(r[3]) : "r"(a));
}
DEV void ldm4t(uint32_t r[4], uint32_t a) {
    asm volatile("ldmatrix.sync.aligned.m8n8.x4.trans.shared.b16 {%0,%1,%2,%3}, [%4];"
                 : "=r"(r[0]), "=r"(r[1]), "=r"(r[2]), "=r"(r[3]) : "r"(a));
}
DEV void mma16816(float d[4], const uint32_t a[4], const uint32_t b[2]) {
    asm volatile("mma.sync.aligned.m16n8k16.row.col.f32.f16.f16.f32 "
                 "{%0,%1,%2,%3}, {%4,%5,%6,%7}, {%8,%9}, {%0,%1,%2,%3};"
                 : "+f"(d[0]), "+f"(d[1]), "+f"(d[2]), "+f"(d[3])
                 : "r"(a[0]), "r"(a[1]), "r"(a[2]), "r"(a[3]), "r"(b[0]), "r"(b[1]));
}
DEV uint32_t packh(float a, float b) {
    __half2 t = __floats2half2_rn(a, b);
    return *reinterpret_cast<uint32_t*>(&t);
}

// mbarrier + TMA
DEV void mbar_init(uint32_t a, uint32_t c) {
    asm volatile("mbarrier.init.shared.b64 [%0], %1;" :: "r"(a), "r"(c) : "memory");
}
DEV void mbar_expect(uint32_t a, uint32_t bytes) {
    asm volatile("mbarrier.arrive.expect_tx.shared.b64 _, [%0], %1;" :: "r"(a), "r"(bytes) : "memory");
}
DEV void mbar_wait(uint32_t a, uint32_t par) {
    asm volatile(
        "{\n\t.reg .pred P;\n"
        "WL_%=:\n\t"
        "mbarrier.try_wait.parity.acquire.cta.shared::cta.b64 P, [%0], %1, 0x989680;\n\t"
        "@P bra WD_%=;\n\t"
        "bra WL_%=;\n"
        "WD_%=:\n\t}"
        :: "r"(a), "r"(par) : "memory");
}
DEV void tma2d(uint32_t dst, const CUtensorMap* m, int c0, int c1, uint32_t mb) {
    asm volatile(
        "cp.async.bulk.tensor.2d.shared::cta.global.tile.mbarrier::complete_tx::bytes "
        "[%0], [%1, {%2, %3}], [%4];"
        :: "r"(dst), "l"(m), "r"(c0), "r"(c1), "r"(mb) : "memory");
}
DEV void fence_async() { asm volatile("fence.proxy.async.shared::cta;" ::: "memory"); }

// PDL primitives
DEV void gdc_wait()   { asm volatile("griddepcontrol.wait;" ::: "memory"); }
DEV void gdc_launch() { asm volatile("griddepcontrol.launch_dependents;" ::: "memory"); }

// ---------------- unified TMA-staged fp16 GEMM ----------------
// A: [M,K] f16 (TMA, SW128), B: [K,N] f16 (TMA, two 64-col halves). fp32 acc.
// MODE 0: Cf = v fp32; if Ab: Ab = relu(bn(v))            [prologue / epilogue]
// MODE 1: Cb = relu(v) f16 (bn1 pre-folded into W1/b1)    [ODE GEMM #1 -> h]
// MODE 3: t = relu(yin + v);                              [Euler block finish]
//         if Cf: Cf = t fp32; if Ab: Ab = relu(bn(t)); if Ch: Ch = t f16
// BIND: B independent of immediate predecessor -> prefetch B via TMA before gdc_wait.
template <int MODE, bool BIND>
__global__ void __launch_bounds__(NTH, 2)
gemm_f16(const __grid_constant__ CUtensorMap mapA,
         const __grid_constant__ CUtensorMap mapB,
         const float* __restrict__ bias,
         const float* __restrict__ mn, const float* __restrict__ iv, const float* __restrict__ bt,
         const float* __restrict__ yin,
         float* __restrict__ Cf, f16* __restrict__ Cb, f16* __restrict__ Ab,
         f16* __restrict__ Ch,
         int K, int N)
{
    extern __shared__ char dsm[];
    __shared__ __align__(8) uint64_t mbar[S_PIPE];

    const int tid = threadIdx.x, lane = tid & 31, warp = tid >> 5;
    const int wm = warp >> 1, wn = warp & 1;
    const int m0 = blockIdx.y * BM, n0 = blockIdx.x * BNT;
    const uint32_t sb = (sptr(dsm) + 1023u) & ~1023u;
    const int KT = K / BK;

    if (tid < S_PIPE) mbar_init(sptr(&mbar[tid]), 1);
    __syncthreads();

    auto issue = [&](int s, int kt) {   // tid 0 only
        const uint32_t st = sb + (uint32_t)s * STAGE;
        const uint32_t mb = sptr(&mbar[s]);
        mbar_expect(mb, STAGE);
        tma2d(st,          &mapA, kt * BK, m0,      mb);
        tma2d(st + 16384u, &mapB, n0,      kt * BK, mb);
        tma2d(st + 24576u, &mapB, n0 + 64, kt * BK, mb);
    };

    if (tid == 0) {
        if constexpr (BIND) {
            // weights (B) written >=2 kernels upstream: prefetch during predecessor tail
            const uint32_t mb0 = sptr(&mbar[0]), mb1 = sptr(&mbar[1]);
            mbar_expect(mb0, STAGE);
            tma2d(sb + 16384u,         &mapB, n0,      0,  mb0);
            tma2d(sb + 24576u,         &mapB, n0 + 64, 0,  mb0);
            mbar_expect(mb1, STAGE);
            tma2d(sb + STAGE + 16384u, &mapB, n0,      BK, mb1);
            tma2d(sb + STAGE + 24576u, &mapB, n0 + 64, BK, mb1);
            gdc_wait();
            tma2d(sb,         &mapA, 0,  m0, mb0);
            tma2d(sb + STAGE, &mapA, BK, m0, mb1);
        } else {
            gdc_wait();
            issue(0, 0);
            issue(1, 1);
        }
    }

    float acc[2][8][4] = {};
    unsigned pb = 0;

    for (int kt = 0; kt < KT; kt++) {
        __syncthreads();                       // all warps done reading the stage being reloaded
        const int nkt = kt + S_PIPE - 1;
        if (tid == 0 && nkt < KT) { fence_async(); issue(nkt % S_PIPE, nkt); }
        const int cs = kt % S_PIPE;
        mbar_wait(sptr(&mbar[cs]), (pb >> cs) & 1u);
        pb ^= 1u << cs;

        const uint32_t sA  = sb + (uint32_t)cs * STAGE;
        const uint32_t sBh = sA + 16384u + ((uint32_t)wn << 13);   // wn * 8192

        // register double-buffered fragment pipeline (SW128 XOR addressing)
        uint32_t aF[2][2][4], bF[2][8][2];
        auto ldf = [&](int bb, int ks) {
            const int kc = ks >> 3;                         // 16B-chunk base index
#pragma unroll
            for (int mt = 0; mt < 2; mt++) {
                const int r = wm * 32 + mt * 16 + (lane & 15);
                const uint32_t cb = (uint32_t)(((kc + (lane >> 4)) ^ (lane & 7)) << 4);
                ldm4(aF[bb][mt], sA + (uint32_t)r * 128u + cb);
            }
#pragma unroll
            for (int np = 0; np < 4; np++) {
                const int r = ks + (((lane >> 3) & 1) << 3) + (lane & 7);
                const uint32_t cb = (uint32_t)((((np << 1) + (lane >> 4)) ^ (lane & 7)) << 4);
                uint32_t t[4];
                ldm4t(t, sBh + (uint32_t)r * 128u + cb);
                bF[bb][np * 2][0] = t[0]; bF[bb][np * 2][1] = t[1];
                bF[bb][np * 2 + 1][0] = t[2]; bF[bb][np * 2 + 1][1] = t[3];
            }
        };
        ldf(0, 0);
#pragma unroll
        for (int ksi = 0; ksi < BK / 16; ksi++) {
            if (ksi + 1 < BK / 16) ldf((ksi + 1) & 1, (ksi + 1) * 16);
            const int cur = ksi & 1;
#pragma unroll
            for (int mt = 0; mt < 2; mt++)
#pragma unroll
                for (int nt = 0; nt < 8; nt++)
                    mma16816(acc[mt][nt], aF[cur][mt], bF[cur][nt]);
        }
    }

    // ---- epilogue ----
#pragma unroll
    for (int mt = 0; mt < 2; mt++) {
        const int row = m0 + wm * 32 + mt * 16 + (lane >> 2);
#pragma unroll
        for (int nt = 0; nt < 8; nt++) {
            const int col = n0 + wn * 64 + nt * 8 + ((lane & 3) << 1);
            const float2 bs = *reinterpret_cast<const float2*>(bias + col);
            float v0 = acc[mt][nt][0] + bs.x;
            float v1 = acc[mt][nt][1] + bs.y;
            float v2 = acc[mt][nt][2] + bs.x;
            float v3 = acc[mt][nt][3] + bs.y;
            const size_t o0 = (size_t)row * N + col;
            const size_t o1 = (size_t)(row + 8) * N + col;

            if constexpr (MODE == 1) {
                v0 = fmaxf(v0, 0.f);
                v1 = fmaxf(v1, 0.f);
                v2 = fmaxf(v2, 0.f);
                v3 = fmaxf(v3, 0.f);
                *reinterpret_cast<uint32_t*>(Cb + o0) = packh(v0, v1);
                *reinterpret_cast<uint32_t*>(Cb + o1) = packh(v2, v3);
            } else if constexpr (MODE == 3) {
                const float2 y0 = *reinterpret_cast<const float2*>(yin + o0);
                const float2 y1 = *reinterpret_cast<const float2*>(yin + o1);
                float t0 = fmaxf(y0.x + v0, 0.f);
                float t1 = fmaxf(y0.y + v1, 0.f);
                float t2v = fmaxf(y1.x + v2, 0.f);
                float t3 = fmaxf(y1.y + v3, 0.f);
                if (Cf) {
                    *reinterpret_cast<float2*>(Cf + o0) = make_float2(t0, t1);
                    *reinterpret_cast<float2*>(Cf + o1) = make_float2(t2v, t3);
                }
                if (Ab) {
                    const float2 m2 = *reinterpret_cast<const float2*>(mn + col);
                    const float2 i2 = *reinterpret_cast<const float2*>(iv + col);
                    const float2 b2v = *reinterpret_cast<const float2*>(bt + col);
                    float a0 = fmaxf((t0 - m2.x) * i2.x + b2v.x, 0.f);
                    float a1 = fmaxf((t1 - m2.y) * i2.y + b2v.y, 0.f);
                    float a2 = fmaxf((t2v - m2.x) * i2.x + b2v.x, 0.f);
                    float a3 = fmaxf((t3 - m2.y) * i2.y + b2v.y, 0.f);
                    *reinterpret_cast<uint32_t*>(Ab + o0) = packh(a0, a1);
                    *reinterpret_cast<uint32_t*>(Ab + o1) = packh(a2, a3);
                }
                if (Ch) {
                    *reinterpret_cast<uint32_t*>(Ch + o0) = packh(t0, t1);
                    *reinterpret_cast<uint32_t*>(Ch + o1) = packh(t2v, t3);
                }
            } else {   // MODE 0
                *reinterpret_cast<float2*>(Cf + o0) = make_float2(v0, v1);
                *reinterpret_cast<float2*>(Cf + o1) = make_float2(v2, v3);
                if (Ab) {
                    const float2 m2 = *reinterpret_cast<const float2*>(mn + col);
                    const float2 i2 = *reinterpret_cast<const float2*>(iv + col);
                    const float2 t2 = *reinterpret_cast<const float2*>(bt + col);
                    float a0 = fmaxf((v0 - m2.x) * i2.x + t2.x, 0.f);
                    float a1 = fmaxf((v1 - m2.y) * i2.y + t2.y, 0.f);
                    float a2 = fmaxf((v2 - m2.x) * i2.x + t2.x, 0.f);
                    float a3 = fmaxf((v3 - m2.y) * i2.y + t2.y, 0.f);
                    *reinterpret_cast<uint32_t*>(Ab + o0) = packh(a0, a1);
                    *reinterpret_cast<uint32_t*>(Ab + o1) = packh(a2, a3);
                }
            }
        }
    }

    gdc_launch();
}

// ---------------- prep kernels (2 launches total) ----------------
__global__ void prep_scalars(const float* __restrict__ gamma, const float* __restrict__ var,
                             const float* __restrict__ b1, const float* __restrict__ mean,
                             const float* __restrict__ beta,
                             float* __restrict__ inv, float* __restrict__ b1f)
{
    int i = blockIdx.x * blockDim.x + threadIdx.x;
    const int NINV = NBLK * 2 * HDIM;
    if (i < NINV) {
        inv[i] = gamma[i] * rsqrtf(var[i] + BN_EPS);
    } else if (i < NINV + NBLK * HDIM) {
        int j = i - NINV;
        int blk = j / HDIM, col = j % HDIM;
        int idx = (blk * 2 + 1) * HDIM + col;
        float ivv = gamma[idx] * rsqrtf(var[idx] + BN_EPS);
        b1f[j] = (b1[j] - mean[idx]) * ivv + beta[idx];
    }
}

constexpr int SEG_X  = BATCH * INDIM / 4;
constexpr int SEG_WI = INDIM * HDIM / 4;
constexpr int SEG_WO = HDIM * OUTDIM / 4;
constexpr int SEG_W1 = NBLK * HDIM * HDIM / 4;
constexpr int SEG_W2 = NBLK * HDIM * HDIM / 4;
constexpr int SEG_TOTAL = SEG_X + SEG_WI + SEG_WO + SEG_W1 + SEG_W2;

__global__ void conv_all(const float* __restrict__ X,  f16* __restrict__ xo,
                         const float* __restrict__ Wi, f16* __restrict__ wio,
                         const float* __restrict__ Wo, f16* __restrict__ woo,
                         const float* __restrict__ W1, f16* __restrict__ w1o,
                         const float* __restrict__ W2, f16* __restrict__ w2o)
{
    int i = blockIdx.x * blockDim.x + threadIdx.x;
    if (i >= SEG_TOTAL) return;
    int j = i;
    if (j < SEG_X) {
        float4 v = reinterpret_cast<const float4*>(X)[j];
        uint2 o; o.x = packh(v.x, v.y); o.y = packh(v.z, v.w);
        reinterpret_cast<uint2*>(xo)[j] = o;
    } else if ((j -= SEG_X) < SEG_WI) {
        float4 v = reinterpret_cast<const float4*>(Wi)[j];
        uint2 o; o.x = packh(v.x, v.y); o.y = packh(v.z, v.w);
        reinterpret_cast<uint2*>(wio)[j] = o;
    } else if ((j -= SEG_WI) < SEG_WO) {
        float4 v = reinterpret_cast<const float4*>(Wo)[j];
        uint2 o; o.x = packh(v.x, v.y); o.y = packh(v.z, v.w);
        reinterpret_cast<uint2*>(woo)[j] = o;
    } else if ((j -= SEG_WO) < SEG_W1) {
        float4 v = reinterpret_cast<const float4*>(W1)[j];
        const int col = (j * 4) & (HDIM - 1);
        const int blk = (j * 4) / (HDIM * HDIM);
        const float4 s4 = *reinterpret_cast<const float4*>(g_inv + (blk * 2 + 1) * HDIM + col);
        uint2 o;
        o.x = packh(v.x * s4.x, v.y * s4.y);
        o.y = packh(v.z * s4.z, v.w * s4.w);
        reinterpret_cast<uint2*>(w1o)[j] = o;
    } else {
        j -= SEG_W1;
        float4 v = reinterpret_cast<const float4*>(W2)[j];
        uint2 o; o.x = packh(v.x, v.y); o.y = packh(v.z, v.w);
        reinterpret_cast<uint2*>(w2o)[j] = o;
    }
}

// ---------------- host ----------------
typedef CUresult (CUDAAPI *PFN_encode)(
    CUtensorMap*, CUtensorMapDataType, cuuint32_t, void*,
    const cuuint64_t*, const cuuint64_t*, const cuuint32_t*, const cuuint32_t*,
    CUtensorMapInterleave, CUtensorMapSwizzle, CUtensorMapL2promotion, CUtensorMapFloatOOBfill);

static PFN_encode get_encoder()
{
    static PFN_encode fn = nullptr;
    if (!fn) {
        void* p = nullptr;
        cudaDriverEntryPointQueryResult st;
        cudaGetDriverEntryPoint("cuTensorMapEncodeTiled", &p, cudaEnableDefault, &st);
        fn = (PFN_encode)p;
    }
    return fn;
}

// rows-major 2D f16 tensor [d1, d0]: dims = {d0, d1}, box = {64, boxRows}
static void enc_map(CUtensorMap* m, void* base, uint64_t d0, uint64_t d1, uint32_t boxRows)
{
    cuuint64_t dims[2]    = {d0, d1};
    cuuint64_t strides[1] = {d0 * 2};
    cuuint32_t box[2]     = {64, boxRows};
    cuuint32_t estr[2]    = {1, 1};
    get_encoder()(m, CU_TENSOR_MAP_DATA_TYPE_FLOAT16, 2, base,
                  dims, strides, box, estr,
                  CU_TENSOR_MAP_INTERLEAVE_NONE, CU_TENSOR_MAP_SWIZZLE_128B,
                  CU_TENSOR_MAP_L2_PROMOTION_L2_128B, CU_TENSOR_MAP_FLOAT_OOB_FILL_NONE);
}

template <int MODE, bool BIND>
static void launch_gemm(dim3 grid,
                        const CUtensorMap& mA, const CUtensorMap& mB, const float* bias,
                        const float* mn, const float* iv, const float* bt,
                        const float* yin,
                        float* Cf, f16* Cb, f16* Ab, f16* Ch,
                        int K, int N)
{
    cudaLaunchConfig_t cfg = {};
    cfg.gridDim = grid;
    cfg.blockDim = dim3(NTH);
    cfg.dynamicSmemBytes = GEMM_SMEM;
    cfg.stream = 0;
    cudaLaunchAttribute at;
    at.id = cudaLaunchAttributeProgrammaticStreamSerialization;
    at.val.programmaticStreamSerializationAllowed = 1;
    cfg.attrs = &at;
    cfg.numAttrs = 1;
    cudaLaunchKernelEx(&cfg, gemm_f16<MODE, BIND>,
                       mA, mB, bias, mn, iv, bt, yin, Cf, Cb, Ab, Ch, K, N);
}

extern "C" void kernel_launch(void* const* d_in, const int* in_sizes, int n_in,
                              void* d_out, int out_size)
{
    const float* X        = (const float*)d_in[0];
    const float* W_in     = (const float*)d_in[1];
    const float* b_in     = (const float*)d_in[2];
    const float* bn_gamma = (const float*)d_in[3];
    const float* bn_beta  = (const float*)d_in[4];
    const float* bn_mean  = (const float*)d_in[5];
    const float* bn_var   = (const float*)d_in[6];
    const float* W1       = (const float*)d_in[7];
    const float* b1       = (const float*)d_in[8];
    const float* W2       = (const float*)d_in[9];
    const float* b2       = (const float*)d_in[10];
    const float* W_out    = (const float*)d_in[11];
    const float* b_out    = (const float*)d_in[12];

    float *y, *inv, *b1f;
    f16 *a, *h, *yh, *x, *w1p, *w2p, *wi, *wo;
    cudaGetSymbolAddress((void**)&y,   g_y);
    cudaGetSymbolAddress((void**)&inv, g_inv);
    cudaGetSymbolAddress((void**)&b1f, g_b1f);
    cudaGetSymbolAddress((void**)&a,   g_a);
    cudaGetSymbolAddress((void**)&h,   g_h);
    cudaGetSymbolAddress((void**)&yh,  g_yh);
    cudaGetSymbolAddress((void**)&x,   g_x);
    cudaGetSymbolAddress((void**)&w1p, g_w1);
    cudaGetSymbolAddress((void**)&w2p, g_w2);
    cudaGetSymbolAddress((void**)&wi,  g_wi);
    cudaGetSymbolAddress((void**)&wo,  g_wo);

    cudaFuncSetAttribute(gemm_f16<0, false>, cudaFuncAttributeMaxDynamicSharedMemorySize, GEMM_SMEM);
    cudaFuncSetAttribute(gemm_f16<0, true>,  cudaFuncAttributeMaxDynamicSharedMemorySize, GEMM_SMEM);
    cudaFuncSetAttribute(gemm_f16<1, true>,  cudaFuncAttributeMaxDynamicSharedMemorySize, GEMM_SMEM);
    cudaFuncSetAttribute(gemm_f16<3, true>,  cudaFuncAttributeMaxDynamicSharedMemorySize, GEMM_SMEM);

    // ---- tensor maps (host-side, capture-time only) ----
    CUtensorMap mX, mA_, mH, mYh, mWi, mWo, mW1[NBLK], mW2[NBLK];
    enc_map(&mX,  x,  INDIM, BATCH, 128);     // A [16384, 512]
    enc_map(&mA_, a,  HDIM,  BATCH, 128);     // A [16384, 1024]
    enc_map(&mH,  h,  HDIM,  BATCH, 128);
    enc_map(&mYh, yh, HDIM,  BATCH, 128);
    enc_map(&mWi, wi, HDIM,  INDIM, 64);      // B [512, 1024]
    enc_map(&mWo, wo, OUTDIM, HDIM, 64);      // B [1024, 512]
    for (int b = 0; b < NBLK; b++) {
        enc_map(&mW1[b], w1p + (size_t)b * HDIM * HDIM, HDIM, HDIM, 64);
        enc_map(&mW2[b], w2p + (size_t)b * HDIM * HDIM, HDIM, HDIM, 64);
    }

    // ---- prep (2 launches, plain) ----
    {
        const int n = NBLK * 2 * HDIM + NBLK * HDIM;
        prep_scalars<<<(n + 255) / 256, 256>>>(bn_gamma, bn_var, b1, bn_mean, bn_beta, inv, b1f);
        conv_all<<<(SEG_TOTAL + 255) / 256, 256>>>(X, x, W_in, wi, W_out, wo, W1, w1p, W2, w2p);
    }

    const dim3 gH(HDIM / BNT, BATCH / BM);     // (8, 128)
    const dim3 gO(OUTDIM / BNT, BATCH / BM);   // (4, 128)

    // ---- prologue: y = X@W_in + b_in; a = relu(bn0_b0(y)) ----
    launch_gemm<0, false>(gH, mX, mWi, b_in,
                          bn_mean, inv, bn_beta, nullptr,
                          y, nullptr, a, nullptr,
                          INDIM, HDIM);

    // ---- Forward Euler per block (h = 1), fully fused ----
    for (int b = 0; b < NBLK; ++b) {
        const float* b1p = b1f + b * HDIM;
        const float* b2p = b2 + b * HDIM;

        launch_gemm<1, true>(gH, mA_, mW1[b], b1p,
                             nullptr, nullptr, nullptr, nullptr,
                             nullptr, h, nullptr, nullptr,
                             HDIM, HDIM);

        const bool final_blk = (b == NBLK - 1);
        const int nb2 = ((b + 1) * 2) % (NBLK * 2);
        launch_gemm<3, true>(gH, mH, mW2[b], b2p,
                             bn_mean + (size_t)nb2 * HDIM,
                             inv + nb2 * HDIM,
                             bn_beta + (size_t)nb2 * HDIM,
                             y,
                             final_blk ? nullptr : y,
                             nullptr,
                             final_blk ? nullptr : a,
                             final_blk ? yh : nullptr,
                             HDIM, HDIM);
    }

    // ---- epilogue: out = y @ W_out + b_out ----
    launch_gemm<0, true>(gO, mYh, mWo, b_out,
                         nullptr, nullptr, nullptr, nullptr,
                         (float*)d_out, nullptr, nullptr, nullptr,
                         HDIM, OUTDIM);
}

// round 15
// speedup vs baseline: 1.2592x; 1.0456x over previous
#include <cuda_runtime.h>
#include <cuda.h>
#include <cuda_fp16.h>
#include <cstdint>
#include <cstddef>

#define DEV __device__ __forceinline__
using f16 = __half;

// ---------------- problem constants ----------------
constexpr int BATCH  = 16384;
constexpr int HDIM   = 1024;
constexpr int INDIM  = 512;
constexpr int OUTDIM = 512;
constexpr int NBLK   = 2;
constexpr float BN_EPS = 1e-3f;

// ---------------- GEMM tiling (R12-proven, TMA staging) ----------------
constexpr int BM  = 128;
constexpr int BNT = 128;
constexpr int BK  = 64;
constexpr int NTH = 256;              // 8 warps: 4 (m) x 2 (n); warp tile 32x64
constexpr int S_PIPE = 3;
constexpr uint32_t STAGE = 32768;     // A 16KB + 2x B-half 8KB (SW128, 128B rows)
constexpr int GEMM_SMEM = S_PIPE * (int)STAGE + 1024;   // 99,328 B -> 2 CTA/SM

// phases: 0..4 have 1024 tiles each (128 mr x 8 nc); phase 5 has 512 (128 x 4)
constexpr int TOTAL_CTAS = 5 * 1024 + 512;   // 5632

// ---------------- persistent device scratch ----------------
__device__ __align__(16) float g_y  [BATCH * HDIM];
__device__ __align__(16) f16   g_a  [BATCH * HDIM];
__device__ __align__(16) f16   g_h  [BATCH * HDIM];
__device__ __align__(16) f16   g_yh [BATCH * HDIM];
__device__ __align__(16) f16   g_x  [BATCH * INDIM];
__device__ __align__(16) f16   g_w1 [NBLK * HDIM * HDIM];  // bn1-folded W1
__device__ __align__(16) f16   g_w2 [NBLK * HDIM * HDIM];
__device__ __align__(16) f16   g_wi [INDIM * HDIM];
__device__ __align__(16) f16   g_wo [HDIM * OUTDIM];
__device__ __align__(16) float g_inv[NBLK * 2 * HDIM];
__device__ __align__(16) float g_b1f[NBLK * HDIM];
__device__ int g_cnt[5 * 128];        // per-phase, per-row-block completion counters

// ---------------- device helpers ----------------
DEV uint32_t sptr(const void* p) { return (uint32_t)__cvta_generic_to_shared(p); }

DEV void ldm4(uint32_t r[4], uint32_t a) {
    asm volatile("ldmatrix.sync.aligned.m8n8.x4.shared.b16 {%0,%1,%2,%3}, [%4];"
                 : "=r"(r[0]), "=r"(r[1]), "=r"(r[2]), "=r"(r[3]) : "r"(a));
}
DEV void ldm4t(uint32_t r[4], uint32_t a) {
    asm volatile("ldmatrix.sync.aligned.m8n8.x4.trans.shared.b16 {%0,%1,%2,%3}, [%4];"
                 : "=r"(r[0]), "=r"(r[1]), "=r"(r[2]), "=r"(r[3]) : "r"(a));
}
DEV void mma16816(float d[4], const uint32_t a[4], const uint32_t b[2]) {
    asm volatile("mma.sync.aligned.m16n8k16.row.col.f32.f16.f16.f32 "
                 "{%0,%1,%2,%3}, {%4,%5,%6,%7}, {%8,%9}, {%0,%1,%2,%3};"
                 : "+f"(d[0]), "+f"(d[1]), "+f"(d[2]), "+f"(d[3])
                 : "r"(a[0]), "r"(a[1]), "r"(a[2]), "r"(a[3]), "r"(b[0]), "r"(b[1]));
}
DEV uint32_t packh(float a, float b) {
    __half2 t = __floats2half2_rn(a, b);
    return *reinterpret_cast<uint32_t*>(&t);
}

DEV void mbar_init(uint32_t a, uint32_t c) {
    asm volatile("mbarrier.init.shared.b64 [%0], %1;" :: "r"(a), "r"(c) : "memory");
}
DEV void mbar_expect(uint32_t a, uint32_t bytes) {
    asm volatile("mbarrier.arrive.expect_tx.shared.b64 _, [%0], %1;" :: "r"(a), "r"(bytes) : "memory");
}
DEV void mbar_wait(uint32_t a, uint32_t par) {
    asm volatile(
        "{\n\t.reg .pred P;\n"
        "WL_%=:\n\t"
        "mbarrier.try_wait.parity.acquire.cta.shared::cta.b64 P, [%0], %1, 0x989680;\n\t"
        "@P bra WD_%=;\n\t"
        "bra WL_%=;\n"
        "WD_%=:\n\t}"
        :: "r"(a), "r"(par) : "memory");
}
DEV void tma2d(uint32_t dst, const CUtensorMap* m, int c0, int c1, uint32_t mb) {
    asm volatile(
        "cp.async.bulk.tensor.2d.shared::cta.global.tile.mbarrier::complete_tx::bytes "
        "[%0], [%1, {%2, %3}], [%4];"
        :: "r"(dst), "l"(m), "r"(c0), "r"(c1), "r"(mb) : "memory");
}
DEV void fence_async() { asm volatile("fence.proxy.async.shared::cta;" ::: "memory"); }

DEV int ld_acq(const int* p) {
    int v;
    asm volatile("ld.acquire.gpu.b32 %0, [%1];" : "=r"(v) : "l"(p) : "memory");
    return v;
}

// ---------------- fused 6-GEMM mega-kernel ----------------
// Phases (each tile = 128x128 of C):
//  0: y = X@Wi + b_in (fp32); a = relu(bn00(y))          [1024 tiles, K=512]
//  1: h = relu(a@W1'[0] + b1f[0])                        [1024, K=1024]
//  2: y = relu(y + h@W2[0] + b2[0]); a = relu(bn10(y))   [1024]
//  3: h = relu(a@W1'[1] + b1f[1])                        [1024]
//  4: t = relu(y + h@W2[1] + b2[1]); yh = f16(t)         [1024]
//  5: out = yh@Wo + b_out (fp32)                         [512, N=512]
// Phase p>=1 tile (mr) spins on cnt[p-1][mr]==8 (all producer column-tiles of
// its row-block), prefetching its weight (B) tiles via TMA while it waits.
// mbarrier protocol: ONE expect_tx(STAGE) per stage barrier; B bytes land
// first, A bytes (issued after the spin) complete the same pending tx.
__global__ void __launch_bounds__(NTH, 2)
mega_f16(const __grid_constant__ CUtensorMap mX,
         const __grid_constant__ CUtensorMap mA_,
         const __grid_constant__ CUtensorMap mH_,
         const __grid_constant__ CUtensorMap mYh_,
         const __grid_constant__ CUtensorMap mWi,
         const __grid_constant__ CUtensorMap mWo,
         const __grid_constant__ CUtensorMap mW1a,
         const __grid_constant__ CUtensorMap mW1b,
         const __grid_constant__ CUtensorMap mW2a,
         const __grid_constant__ CUtensorMap mW2b,
         const float* __restrict__ bn_mean, const float* __restrict__ inv,
         const float* __restrict__ bn_beta,
         const float* __restrict__ b_in, const float* __restrict__ b1f,
         const float* __restrict__ b2, const float* __restrict__ b_out,
         float* __restrict__ y, f16* __restrict__ a, f16* __restrict__ h,
         f16* __restrict__ yh, float* __restrict__ out)
{
    extern __shared__ char dsm[];
    __shared__ __align__(8) uint64_t mbar[S_PIPE];

    const int tid = threadIdx.x, lane = tid & 31, warp = tid >> 5;
    const int wm = warp >> 1, wn = warp & 1;
    const uint32_t sb = (sptr(dsm) + 1023u) & ~1023u;

    // ---- phase / tile resolution (pure shift/mask) ----
    const int bid = blockIdx.x;
    const int ph = min(bid >> 10, 5);            // phases 0..4 of 1024; 5 has 512
    const int t = bid & 1023;                    // phase-local tile index
    const int colshift = (ph == 5) ? 2 : 3;
    const int mr = t >> colshift;
    const int nc = t & ((1 << colshift) - 1);
    const int m0 = mr * BM, n0 = nc * BNT;
    const int KT = (ph == 0) ? (INDIM / BK) : (HDIM / BK);

    const CUtensorMap* pA;
    const CUtensorMap* pB;
    switch (ph) {
        case 0:  pA = &mX;   pB = &mWi;  break;
        case 1:  pA = &mA_;  pB = &mW1a; break;
        case 2:  pA = &mH_;  pB = &mW2a; break;
        case 3:  pA = &mA_;  pB = &mW1b; break;
        case 4:  pA = &mH_;  pB = &mW2b; break;
        default: pA = &mYh_; pB = &mWo;  break;
    }

    if (tid < S_PIPE) mbar_init(sptr(&mbar[tid]), 1);
    __syncthreads();

    auto issue = [&](int s, int kt) {   // tid 0 only: full stage (A + B), one expect
        const uint32_t st = sb + (uint32_t)s * STAGE;
        const uint32_t mb = sptr(&mbar[s]);
        mbar_expect(mb, STAGE);
        tma2d(st,          pA, kt * BK, m0,      mb);
        tma2d(st + 16384u, pB, n0,      kt * BK, mb);
        tma2d(st + 24576u, pB, n0 + 64, kt * BK, mb);
    };

    if (tid == 0) {
        const uint32_t mb0 = sptr(&mbar[0]), mb1 = sptr(&mbar[1]);
        // ONE expect per stage barrier for the FULL stage bytes (R12 protocol).
        // B (weights) prefetched now — they depend only on conv_all (stream-ordered).
        mbar_expect(mb0, STAGE);
        tma2d(sb + 16384u,         pB, n0,      0,  mb0);
        tma2d(sb + 24576u,         pB, n0 + 64, 0,  mb0);
        mbar_expect(mb1, STAGE);
        tma2d(sb + STAGE + 16384u, pB, n0,      BK, mb1);
        tma2d(sb + STAGE + 24576u, pB, n0 + 64, BK, mb1);
        // wait for producer row-block (phases 1..5)
        if (ph > 0) {
            const int* c = &g_cnt[(ph - 1) * 128 + mr];
            while (ld_acq(c) < 8) __nanosleep(64);
        }
        // A operand now safe; bytes complete the SAME pending tx (no new expect)
        tma2d(sb,         pA, 0,  m0, mb0);
        tma2d(sb + STAGE, pA, BK, m0, mb1);
    }

    float acc[2][8][4] = {};
    unsigned pb = 0;

    for (int kt = 0; kt < KT; kt++) {
        __syncthreads();                       // all warps done reading the stage being reloaded
        const int nkt = kt + S_PIPE - 1;
        if (tid == 0 && nkt < KT) { fence_async(); issue(nkt % S_PIPE, nkt); }
        const int cs = kt % S_PIPE;
        mbar_wait(sptr(&mbar[cs]), (pb >> cs) & 1u);
        pb ^= 1u << cs;

        const uint32_t sA  = sb + (uint32_t)cs * STAGE;
        const uint32_t sBh = sA + 16384u + ((uint32_t)wn << 13);

        uint32_t aF[2][2][4], bF[2][8][2];
        auto ldf = [&](int bb, int ks) {
            const int kc = ks >> 3;
#pragma unroll
            for (int mt = 0; mt < 2; mt++) {
                const int r = wm * 32 + mt * 16 + (lane & 15);
                const uint32_t cb = (uint32_t)(((kc + (lane >> 4)) ^ (lane & 7)) << 4);
                ldm4(aF[bb][mt], sA + (uint32_t)r * 128u + cb);
            }
#pragma unroll
            for (int np = 0; np < 4; np++) {
                const int r = ks + (((lane >> 3) & 1) << 3) + (lane & 7);
                const uint32_t cb = (uint32_t)((((np << 1) + (lane >> 4)) ^ (lane & 7)) << 4);
                uint32_t tt[4];
                ldm4t(tt, sBh + (uint32_t)r * 128u + cb);
                bF[bb][np * 2][0] = tt[0]; bF[bb][np * 2][1] = tt[1];
                bF[bb][np * 2 + 1][0] = tt[2]; bF[bb][np * 2 + 1][1] = tt[3];
            }
        };
        ldf(0, 0);
#pragma unroll
        for (int ksi = 0; ksi < BK / 16; ksi++) {
            if (ksi + 1 < BK / 16) ldf((ksi + 1) & 1, (ksi + 1) * 16);
            const int cur = ksi & 1;
#pragma unroll
            for (int mt = 0; mt < 2; mt++)
#pragma unroll
                for (int nt = 0; nt < 8; nt++)
                    mma16816(acc[mt][nt], aF[cur][mt], bF[cur][nt]);
        }
    }

    // ---- epilogue: resolve phase outputs (recomputed; keeps loop regs lean) ----
    const int Nc = (ph == 5) ? OUTDIM : HDIM;
    const float* bias; const float* mnp = nullptr; const float* ivp = nullptr;
    const float* btp = nullptr; const float* yin = nullptr;
    float* Cf = nullptr; f16* Cb = nullptr; f16* Abp = nullptr; f16* Chp = nullptr;
    int mode;
    switch (ph) {
        case 0:  mode = 0; bias = b_in;        Cf = y;  Abp = a;
                 mnp = bn_mean; ivp = inv; btp = bn_beta;            break;
        case 1:  mode = 1; bias = b1f;         Cb = h;               break;
        case 2:  mode = 3; bias = b2;          yin = y; Cf = y; Abp = a;
                 mnp = bn_mean + 2 * HDIM; ivp = inv + 2 * HDIM; btp = bn_beta + 2 * HDIM; break;
        case 3:  mode = 1; bias = b1f + HDIM;  Cb = h;               break;
        case 4:  mode = 3; bias = b2 + HDIM;   yin = y; Chp = yh;    break;
        default: mode = 0; bias = b_out;       Cf = out;             break;
    }

#pragma unroll
    for (int mt = 0; mt < 2; mt++) {
        const int row = m0 + wm * 32 + mt * 16 + (lane >> 2);
#pragma unroll
        for (int nt = 0; nt < 8; nt++) {
            const int col = n0 + wn * 64 + nt * 8 + ((lane & 3) << 1);
            const float2 bs = *reinterpret_cast<const float2*>(bias + col);
            float v0 = acc[mt][nt][0] + bs.x;
            float v1 = acc[mt][nt][1] + bs.y;
            float v2 = acc[mt][nt][2] + bs.x;
            float v3 = acc[mt][nt][3] + bs.y;
            const size_t o0 = (size_t)row * Nc + col;
            const size_t o1 = (size_t)(row + 8) * Nc + col;

            if (mode == 1) {
                *reinterpret_cast<uint32_t*>(Cb + o0) = packh(fmaxf(v0, 0.f), fmaxf(v1, 0.f));
                *reinterpret_cast<uint32_t*>(Cb + o1) = packh(fmaxf(v2, 0.f), fmaxf(v3, 0.f));
            } else if (mode == 3) {
                const float2 y0 = *reinterpret_cast<const float2*>(yin + o0);
                const float2 y1 = *reinterpret_cast<const float2*>(yin + o1);
                float t0 = fmaxf(y0.x + v0, 0.f);
                float t1 = fmaxf(y0.y + v1, 0.f);
                float t2v = fmaxf(y1.x + v2, 0.f);
                float t3 = fmaxf(y1.y + v3, 0.f);
                if (Cf) {
                    *reinterpret_cast<float2*>(Cf + o0) = make_float2(t0, t1);
                    *reinterpret_cast<float2*>(Cf + o1) = make_float2(t2v, t3);
                }
                if (Abp) {
                    const float2 m2 = *reinterpret_cast<const float2*>(mnp + col);
                    const float2 i2 = *reinterpret_cast<const float2*>(ivp + col);
                    const float2 bb2 = *reinterpret_cast<const float2*>(btp + col);
                    *reinterpret_cast<uint32_t*>(Abp + o0) =
                        packh(fmaxf((t0 - m2.x) * i2.x + bb2.x, 0.f),
                              fmaxf((t1 - m2.y) * i2.y + bb2.y, 0.f));
                    *reinterpret_cast<uint32_t*>(Abp + o1) =
                        packh(fmaxf((t2v - m2.x) * i2.x + bb2.x, 0.f),
                              fmaxf((t3 - m2.y) * i2.y + bb2.y, 0.f));
                }
                if (Chp) {
                    *reinterpret_cast<uint32_t*>(Chp + o0) = packh(t0, t1);
                    *reinterpret_cast<uint32_t*>(Chp + o1) = packh(t2v, t3);
                }
            } else {   // mode 0
                *reinterpret_cast<float2*>(Cf + o0) = make_float2(v0, v1);
                *reinterpret_cast<float2*>(Cf + o1) = make_float2(v2, v3);
                if (Abp) {
                    const float2 m2 = *reinterpret_cast<const float2*>(mnp + col);
                    const float2 i2 = *reinterpret_cast<const float2*>(ivp + col);
                    const float2 bb2 = *reinterpret_cast<const float2*>(btp + col);
                    *reinterpret_cast<uint32_t*>(Abp + o0) =
                        packh(fmaxf((v0 - m2.x) * i2.x + bb2.x, 0.f),
                              fmaxf((v1 - m2.y) * i2.y + bb2.y, 0.f));
                    *reinterpret_cast<uint32_t*>(Abp + o1) =
                        packh(fmaxf((v2 - m2.x) * i2.x + bb2.x, 0.f),
                              fmaxf((v3 - m2.y) * i2.y + bb2.y, 0.f));
                }
            }
        }
    }

    // ---- signal completion (release) ----
    __syncthreads();
    if (tid == 0 && ph < 5) {
        __threadfence();
        atomicAdd(&g_cnt[ph * 128 + mr], 1);
    }
}

// ---------------- prep kernels (2 launches) ----------------
__global__ void prep_scalars(const float* __restrict__ gamma, const float* __restrict__ var,
                             const float* __restrict__ b1, const float* __restrict__ mean,
                             const float* __restrict__ beta,
                             float* __restrict__ inv, float* __restrict__ b1f)
{
    int i = blockIdx.x * blockDim.x + threadIdx.x;
    const int NINV = NBLK * 2 * HDIM;
    const int NB1  = NBLK * HDIM;
    if (i < NINV) {
        inv[i] = gamma[i] * rsqrtf(var[i] + BN_EPS);
    } else if (i < NINV + NB1) {
        int j = i - NINV;
        int blk = j / HDIM, col = j % HDIM;
        int idx = (blk * 2 + 1) * HDIM + col;
        float ivv = gamma[idx] * rsqrtf(var[idx] + BN_EPS);
        b1f[j] = (b1[j] - mean[idx]) * ivv + beta[idx];
    } else if (i < NINV + NB1 + 5 * 128) {
        g_cnt[i - NINV - NB1] = 0;      // zero producer/consumer counters
    }
}

constexpr int SEG_X  = BATCH * INDIM / 4;
constexpr int SEG_WI = INDIM * HDIM / 4;
constexpr int SEG_WO = HDIM * OUTDIM / 4;
constexpr int SEG_W1 = NBLK * HDIM * HDIM / 4;
constexpr int SEG_W2 = NBLK * HDIM * HDIM / 4;
constexpr int SEG_TOTAL = SEG_X + SEG_WI + SEG_WO + SEG_W1 + SEG_W2;

__global__ void conv_all(const float* __restrict__ X,  f16* __restrict__ xo,
                         const float* __restrict__ Wi, f16* __restrict__ wio,
                         const float* __restrict__ Wo, f16* __restrict__ woo,
                         const float* __restrict__ W1, f16* __restrict__ w1o,
                         const float* __restrict__ W2, f16* __restrict__ w2o)
{
    int i = blockIdx.x * blockDim.x + threadIdx.x;
    if (i >= SEG_TOTAL) return;
    int j = i;
    if (j < SEG_X) {
        float4 v = reinterpret_cast<const float4*>(X)[j];
        uint2 o; o.x = packh(v.x, v.y); o.y = packh(v.z, v.w);
        reinterpret_cast<uint2*>(xo)[j] = o;
    } else if ((j -= SEG_X) < SEG_WI) {
        float4 v = reinterpret_cast<const float4*>(Wi)[j];
        uint2 o; o.x = packh(v.x, v.y); o.y = packh(v.z, v.w);
        reinterpret_cast<uint2*>(wio)[j] = o;
    } else if ((j -= SEG_WI) < SEG_WO) {
        float4 v = reinterpret_cast<const float4*>(Wo)[j];
        uint2 o; o.x = packh(v.x, v.y); o.y = packh(v.z, v.w);
        reinterpret_cast<uint2*>(woo)[j] = o;
    } else if ((j -= SEG_WO) < SEG_W1) {
        float4 v = reinterpret_cast<const float4*>(W1)[j];
        const int col = (j * 4) & (HDIM - 1);
        const int blk = (j * 4) / (HDIM * HDIM);
        const float4 s4 = *reinterpret_cast<const float4*>(g_inv + (blk * 2 + 1) * HDIM + col);
        uint2 o;
        o.x = packh(v.x * s4.x, v.y * s4.y);
        o.y = packh(v.z * s4.z, v.w * s4.w);
        reinterpret_cast<uint2*>(w1o)[j] = o;
    } else {
        j -= SEG_W1;
        float4 v = reinterpret_cast<const float4*>(W2)[j];
        uint2 o; o.x = packh(v.x, v.y); o.y = packh(v.z, v.w);
        reinterpret_cast<uint2*>(w2o)[j] = o;
    }
}

// ---------------- host ----------------
typedef CUresult (CUDAAPI *PFN_encode)(
    CUtensorMap*, CUtensorMapDataType, cuuint32_t, void*,
    const cuuint64_t*, const cuuint64_t*, const cuuint32_t*, const cuuint32_t*,
    CUtensorMapInterleave, CUtensorMapSwizzle, CUtensorMapL2promotion, CUtensorMapFloatOOBfill);

static PFN_encode get_encoder()
{
    static PFN_encode fn = nullptr;
    if (!fn) {
        void* p = nullptr;
        cudaDriverEntryPointQueryResult st;
        cudaGetDriverEntryPoint("cuTensorMapEncodeTiled", &p, cudaEnableDefault, &st);
        fn = (PFN_encode)p;
    }
    return fn;
}

static void enc_map(CUtensorMap* m, void* base, uint64_t d0, uint64_t d1, uint32_t boxRows)
{
    cuuint64_t dims[2]    = {d0, d1};
    cuuint64_t strides[1] = {d0 * 2};
    cuuint32_t box[2]     = {64, boxRows};
    cuuint32_t estr[2]    = {1, 1};
    get_encoder()(m, CU_TENSOR_MAP_DATA_TYPE_FLOAT16, 2, base,
                  dims, strides, box, estr,
                  CU_TENSOR_MAP_INTERLEAVE_NONE, CU_TENSOR_MAP_SWIZZLE_128B,
                  CU_TENSOR_MAP_L2_PROMOTION_L2_128B, CU_TENSOR_MAP_FLOAT_OOB_FILL_NONE);
}

extern "C" void kernel_launch(void* const* d_in, const int* in_sizes, int n_in,
                              void* d_out, int out_size)
{
    const float* X        = (const float*)d_in[0];
    const float* W_in     = (const float*)d_in[1];
    const float* b_in     = (const float*)d_in[2];
    const float* bn_gamma = (const float*)d_in[3];
    const float* bn_beta  = (const float*)d_in[4];
    const float* bn_mean  = (const float*)d_in[5];
    const float* bn_var   = (const float*)d_in[6];
    const float* W1       = (const float*)d_in[7];
    const float* b1       = (const float*)d_in[8];
    const float* W2       = (const float*)d_in[9];
    const float* b2       = (const float*)d_in[10];
    const float* W_out    = (const float*)d_in[11];
    const float* b_out    = (const float*)d_in[12];

    float *y, *inv, *b1f;
    f16 *a, *h, *yh, *x, *w1p, *w2p, *wi, *wo;
    cudaGetSymbolAddress((void**)&y,   g_y);
    cudaGetSymbolAddress((void**)&inv, g_inv);
    cudaGetSymbolAddress((void**)&b1f, g_b1f);
    cudaGetSymbolAddress((void**)&a,   g_a);
    cudaGetSymbolAddress((void**)&h,   g_h);
    cudaGetSymbolAddress((void**)&yh,  g_yh);
    cudaGetSymbolAddress((void**)&x,   g_x);
    cudaGetSymbolAddress((void**)&w1p, g_w1);
    cudaGetSymbolAddress((void**)&w2p, g_w2);
    cudaGetSymbolAddress((void**)&wi,  g_wi);
    cudaGetSymbolAddress((void**)&wo,  g_wo);

    cudaFuncSetAttribute(mega_f16, cudaFuncAttributeMaxDynamicSharedMemorySize, GEMM_SMEM);

    // ---- tensor maps (host-side, capture-time constants) ----
    CUtensorMap mX, mA_, mH_, mYh_, mWi, mWo, mW1[NBLK], mW2[NBLK];
    enc_map(&mX,   x,  INDIM,  BATCH, 128);
    enc_map(&mA_,  a,  HDIM,   BATCH, 128);
    enc_map(&mH_,  h,  HDIM,   BATCH, 128);
    enc_map(&mYh_, yh, HDIM,   BATCH, 128);
    enc_map(&mWi,  wi, HDIM,   INDIM, 64);
    enc_map(&mWo,  wo, OUTDIM, HDIM,  64);
    for (int b = 0; b < NBLK; b++) {
        enc_map(&mW1[b], w1p + (size_t)b * HDIM * HDIM, HDIM, HDIM, 64);
        enc_map(&mW2[b], w2p + (size_t)b * HDIM * HDIM, HDIM, HDIM, 64);
    }

    // ---- prep ----
    {
        const int n = NBLK * 2 * HDIM + NBLK * HDIM + 5 * 128;
        prep_scalars<<<(n + 255) / 256, 256>>>(bn_gamma, bn_var, b1, bn_mean, bn_beta, inv, b1f);
        conv_all<<<(SEG_TOTAL + 255) / 256, 256>>>(X, x, W_in, wi, W_out, wo, W1, w1p, W2, w2p);
    }

    // ---- fused 6-GEMM pipeline in a single launch ----
    mega_f16<<<TOTAL_CTAS, NTH, GEMM_SMEM>>>(
        mX, mA_, mH_, mYh_, mWi, mWo, mW1[0], mW1[1], mW2[0], mW2[1],
        bn_mean, inv, bn_beta,
        b_in, b1f, b2, b_out,
        y, a, h, yh, (float*)d_out);
}